// round 1
// baseline (speedup 1.0000x reference)
#include <cuda_runtime.h>
#include <math_constants.h>

#define SQ 2048
#define NB 4
#define ND 256
#define NE 256
#define NH 8
#define HD 32
#define MROWS (SQ*NB)       // 8192
#define LDQKV (3*NE)        // 768
#define QB 32
#define MAXW 160

// ---------------- scratch (device globals; no allocation) ----------------
__device__ float g_Weff[3*NE*ND];          // stacked (Win_q@Wq; Win_k@Wk; Win_v@Wv)  [768,256]
__device__ float g_beff[3*NE];
__device__ float g_Wcomb[ND*NE];           // Wfc @ Wout  [256,256]
__device__ float g_bcomb[ND];
__device__ float g_qkv[(size_t)MROWS*LDQKV];
__device__ float g_ctx[(size_t)MROWS*NE];
__device__ float g_y[(size_t)MROWS*ND];

// ---------------- weight fusion ----------------
// Weff_t = Win[t] @ Wt ; beff_t = Win[t]@bt + bin_t ; Wcomb = Wfc @ Wout ; bcomb = Wfc@bout + bfc
__global__ void prep_kernel(const float* __restrict__ Wq, const float* __restrict__ bq,
                            const float* __restrict__ Wk, const float* __restrict__ bk,
                            const float* __restrict__ Wv, const float* __restrict__ bv,
                            const float* __restrict__ Win, const float* __restrict__ bin_,
                            const float* __restrict__ Wout, const float* __restrict__ bout,
                            const float* __restrict__ Wfc, const float* __restrict__ bfc)
{
    int idx = blockIdx.x * blockDim.x + threadIdx.x;
    const int NW = 4 * NE * ND;   // 262144
    if (idx < NW) {
        int t = idx >> 16;
        int r = (idx >> 8) & 255;
        int d = idx & 255;
        float acc = 0.f;
        if (t < 3) {
            const float* Wt = (t == 0) ? Wq : (t == 1) ? Wk : Wv;
            const float* wr = Win + (size_t)(t*NE + r) * NE;
            #pragma unroll 8
            for (int c = 0; c < NE; c++) acc += wr[c] * Wt[c*ND + d];
            g_Weff[(size_t)(t*NE + r)*ND + d] = acc;
        } else {
            const float* fr = Wfc + (size_t)r * NE;
            #pragma unroll 8
            for (int c = 0; c < NE; c++) acc += fr[c] * Wout[c*NE + d];
            g_Wcomb[(size_t)r*NE + d] = acc;
        }
    } else {
        int j = idx - NW;
        if (j < 3*NE) {
            int t = j >> 8;
            const float* bt = (t == 0) ? bq : (t == 1) ? bk : bv;
            const float* wr = Win + (size_t)j * NE;
            float acc = bin_[j];
            for (int c = 0; c < NE; c++) acc += wr[c] * bt[c];
            g_beff[j] = acc;
        } else if (j < 3*NE + ND) {
            int r = j - 3*NE;
            const float* fr = Wfc + (size_t)r * NE;
            float acc = bfc[r];
            for (int c = 0; c < NE; c++) acc += fr[c] * bout[c];
            g_bcomb[r] = acc;
        }
    }
}

// ---------------- GEMM: C[M,N] = A[M,K] @ W[N,K]^T + bias (+residual) ----------------
// 64x64 block tile, BK=16, 256 threads, 4x4 per-thread microtile. Shapes assumed multiples.
__global__ void gemm64(const float* __restrict__ A, const float* __restrict__ W,
                       const float* __restrict__ bias, const float* __restrict__ resid,
                       float* __restrict__ C, int N, int K)
{
    __shared__ __align__(16) float As[16][68];
    __shared__ __align__(16) float Ws[16][68];
    const int t    = threadIdx.x;
    const int m0   = blockIdx.y * 64;
    const int n0   = blockIdx.x * 64;
    const int lrow = t >> 2;
    const int lc4  = (t & 3) << 2;
    const int ty   = t >> 4;    // 0..15
    const int tx   = t & 15;

    float acc[4][4] = {};
    const float* Ap = A + (size_t)(m0 + lrow) * K + lc4;
    const float* Wp = W + (size_t)(n0 + lrow) * K + lc4;

    for (int k0 = 0; k0 < K; k0 += 16) {
        float4 av = *(const float4*)(Ap + k0);
        float4 wv = *(const float4*)(Wp + k0);
        As[lc4+0][lrow] = av.x; As[lc4+1][lrow] = av.y;
        As[lc4+2][lrow] = av.z; As[lc4+3][lrow] = av.w;
        Ws[lc4+0][lrow] = wv.x; Ws[lc4+1][lrow] = wv.y;
        Ws[lc4+2][lrow] = wv.z; Ws[lc4+3][lrow] = wv.w;
        __syncthreads();
        #pragma unroll
        for (int kk = 0; kk < 16; kk++) {
            float4 a4 = *(const float4*)&As[kk][ty << 2];
            float4 w4 = *(const float4*)&Ws[kk][tx << 2];
            float ar[4] = {a4.x, a4.y, a4.z, a4.w};
            float wr[4] = {w4.x, w4.y, w4.z, w4.w};
            #pragma unroll
            for (int i = 0; i < 4; i++)
                #pragma unroll
                for (int j = 0; j < 4; j++)
                    acc[i][j] += ar[i] * wr[j];
        }
        __syncthreads();
    }

    float4 b4 = *(const float4*)&bias[n0 + (tx << 2)];
    #pragma unroll
    for (int i = 0; i < 4; i++) {
        int mrow = m0 + (ty << 2) + i;
        float4 o;
        o.x = acc[i][0] + b4.x; o.y = acc[i][1] + b4.y;
        o.z = acc[i][2] + b4.z; o.w = acc[i][3] + b4.w;
        if (resid) {
            float4 r4 = *(const float4*)&resid[(size_t)mrow * N + n0 + (tx << 2)];
            o.x += r4.x; o.y += r4.y; o.z += r4.z; o.w += r4.w;
        }
        *(float4*)&C[(size_t)mrow * N + n0 + (tx << 2)] = o;
    }
}

// ---------------- banded attention ----------------
// grid: (SQ/QB, NB*NH), 256 threads (8 warps, 4 queries each). Warp-per-query, lane = head dim.
__global__ void attn_kernel(const int* __restrict__ reqp, float* __restrict__ ctx)
{
    __shared__ float sk[MAXW * HD];
    __shared__ float sv[MAXW * HD];
    const float* qkv = g_qkv;
    const int req = *reqp;
    const int bh = blockIdx.y;
    const int b = bh / NH;
    const int h = bh % NH;
    const int hoff = h * HD;
    const int q0 = blockIdx.x * QB;
    const int w0 = max(0, q0 - (req - 1));
    const int w1 = min(SQ - 1, q0 + QB - 1 + (req - 1));
    const int cw = w1 - w0 + 1;
    const bool stg = (cw <= MAXW);

    if (stg) {
        for (int e = threadIdx.x; e < cw * HD; e += blockDim.x) {
            int r = e >> 5, d = e & 31;
            size_t base = (size_t)((w0 + r) * NB + b) * LDQKV + hoff + d;
            sk[e] = qkv[base + NE];
            sv[e] = qkv[base + 2 * NE];
        }
        __syncthreads();
    }

    const int warp = threadIdx.x >> 5;
    const int lane = threadIdx.x & 31;
    const float scale = rsqrtf((float)HD);

    for (int tq = 0; tq < QB / 8; tq++) {
        int i = q0 + warp * (QB / 8) + tq;
        float qv = qkv[(size_t)(i * NB + b) * LDQKV + hoff + lane];
        int jlo = max(0, i - req + 1);
        int jhi = min(SQ - 1, i + req - 1);
        int cnt = jhi - jlo + 1;   // <= 2*req-1 (supports req<=64)

        float sc[4] = {-CUDART_INF_F, -CUDART_INF_F, -CUDART_INF_F, -CUDART_INF_F};
        for (int jj = 0; jj < cnt; jj++) {
            int j = jlo + jj;
            float kd = stg ? sk[(j - w0) * HD + lane]
                           : qkv[(size_t)(j * NB + b) * LDQKV + hoff + lane + NE];
            float p = qv * kd;
            p += __shfl_xor_sync(0xffffffffu, p, 16);
            p += __shfl_xor_sync(0xffffffffu, p, 8);
            p += __shfl_xor_sync(0xffffffffu, p, 4);
            p += __shfl_xor_sync(0xffffffffu, p, 2);
            p += __shfl_xor_sync(0xffffffffu, p, 1);
            if (lane == (jj & 31)) sc[jj >> 5] = p * scale;
        }

        float mx = fmaxf(fmaxf(sc[0], sc[1]), fmaxf(sc[2], sc[3]));
        mx = fmaxf(mx, __shfl_xor_sync(0xffffffffu, mx, 16));
        mx = fmaxf(mx, __shfl_xor_sync(0xffffffffu, mx, 8));
        mx = fmaxf(mx, __shfl_xor_sync(0xffffffffu, mx, 4));
        mx = fmaxf(mx, __shfl_xor_sync(0xffffffffu, mx, 2));
        mx = fmaxf(mx, __shfl_xor_sync(0xffffffffu, mx, 1));

        float p[4];
        float sum = 0.f;
        #pragma unroll
        for (int u = 0; u < 4; u++) {
            int jj = u * 32 + lane;
            p[u] = (jj < cnt) ? __expf(sc[u] - mx) : 0.f;
            sum += p[u];
        }
        sum += __shfl_xor_sync(0xffffffffu, sum, 16);
        sum += __shfl_xor_sync(0xffffffffu, sum, 8);
        sum += __shfl_xor_sync(0xffffffffu, sum, 4);
        sum += __shfl_xor_sync(0xffffffffu, sum, 2);
        sum += __shfl_xor_sync(0xffffffffu, sum, 1);

        float acc = 0.f;
        for (int jj = 0; jj < cnt; jj++) {
            float pj = __shfl_sync(0xffffffffu, p[jj >> 5], jj & 31);
            float vd = stg ? sv[(jlo - w0 + jj) * HD + lane]
                           : qkv[(size_t)((jlo + jj) * NB + b) * LDQKV + hoff + lane + 2 * NE];
            acc += pj * vd;
        }
        ctx[(size_t)(i * NB + b) * NE + hoff + lane] = acc / sum;
    }
}

// ---------------- layernorm (warp per row of 256) ----------------
__global__ void ln_kernel(const float* __restrict__ gamma, const float* __restrict__ beta,
                          float* __restrict__ out)
{
    int row = blockIdx.x * 8 + (threadIdx.x >> 5);
    int lane = threadIdx.x & 31;
    const float* yr = g_y + (size_t)row * ND;
    float v[8], s = 0.f, s2 = 0.f;
    #pragma unroll
    for (int u = 0; u < 8; u++) {
        v[u] = yr[u * 32 + lane];
        s += v[u];
        s2 += v[u] * v[u];
    }
    #pragma unroll
    for (int o = 16; o >= 1; o >>= 1) {
        s  += __shfl_xor_sync(0xffffffffu, s, o);
        s2 += __shfl_xor_sync(0xffffffffu, s2, o);
    }
    float mu  = s * (1.f / ND);
    float var = s2 * (1.f / ND) - mu * mu;
    float inv = rsqrtf(var + 1e-6f);
    #pragma unroll
    for (int u = 0; u < 8; u++) {
        int c = u * 32 + lane;
        out[(size_t)row * ND + c] = (v[u] - mu) * inv * gamma[c] + beta[c];
    }
}

// ---------------- launch ----------------
extern "C" void kernel_launch(void* const* d_in, const int* in_sizes, int n_in,
                              void* d_out, int out_size)
{
    const float* mod  = (const float*)d_in[0];
    // d_in[1] = mask (unused in this branch)
    const float* Wq   = (const float*)d_in[2];
    const float* bq   = (const float*)d_in[3];
    const float* Wk   = (const float*)d_in[4];
    const float* bk   = (const float*)d_in[5];
    const float* Wv   = (const float*)d_in[6];
    const float* bv   = (const float*)d_in[7];
    const float* Win  = (const float*)d_in[8];
    const float* bin_ = (const float*)d_in[9];
    const float* Wout = (const float*)d_in[10];
    const float* bout = (const float*)d_in[11];
    const float* Wfc  = (const float*)d_in[12];
    const float* bfc  = (const float*)d_in[13];
    const float* gamma= (const float*)d_in[14];
    const float* beta = (const float*)d_in[15];
    const int*   req  = (const int*)d_in[16];
    float* out = (float*)d_out;

    float *dWeff, *dbeff, *dWcomb, *dbcomb, *dqkv, *dctx, *dy;
    cudaGetSymbolAddress((void**)&dWeff,  g_Weff);
    cudaGetSymbolAddress((void**)&dbeff,  g_beff);
    cudaGetSymbolAddress((void**)&dWcomb, g_Wcomb);
    cudaGetSymbolAddress((void**)&dbcomb, g_bcomb);
    cudaGetSymbolAddress((void**)&dqkv,   g_qkv);
    cudaGetSymbolAddress((void**)&dctx,   g_ctx);
    cudaGetSymbolAddress((void**)&dy,     g_y);

    // 1. fold weights: (Win_q@Wq etc.) and (Wfc@Wout)
    prep_kernel<<<(4*NE*ND + 3*NE + ND + 255) / 256, 256>>>(
        Wq, bq, Wk, bk, Wv, bv, Win, bin_, Wout, bout, Wfc, bfc);

    // 2. fused qkv projection: [8192,256] @ [768,256]^T
    gemm64<<<dim3(LDQKV / 64, MROWS / 64), 256>>>(mod, dWeff, dbeff, nullptr, dqkv, LDQKV, ND);

    // 3. banded attention
    attn_kernel<<<dim3(SQ / QB, NB * NH), 256>>>(req, dctx);

    // 4. fused out_proj+fc with residual: ctx @ (Wfc@Wout)^T + bcomb + mod
    gemm64<<<dim3(ND / 64, MROWS / 64), 256>>>(dctx, dWcomb, dbcomb, mod, dy, ND, NE);

    // 5. layernorm
    ln_kernel<<<MROWS / 8, 256>>>(gamma, beta, out);
}

// round 2
// speedup vs baseline: 1.0195x; 1.0195x over previous
#include <cuda_runtime.h>
#include <math_constants.h>
#include <cstdint>

#define SQ 2048
#define NB 4
#define ND 256
#define NE 256
#define NH 8
#define HD 32
#define MROWS (SQ*NB)       // 8192
#define LDQKV (3*NE)        // 768
#define QB 32
#define MAXW 160

// ---------------- scratch (device globals; no allocation) ----------------
__device__ float g_Weff[3*NE*ND];          // stacked (Win_q@Wq; Win_k@Wk; Win_v@Wv)  [768,256]
__device__ float g_beff[3*NE];
__device__ float g_Wcomb[ND*NE];           // Wfc @ Wout  [256,256]
__device__ float g_bcomb[ND];
__device__ float g_qkv[(size_t)MROWS*LDQKV];
__device__ float g_ctx[(size_t)MROWS*NE];
__device__ float g_y[(size_t)MROWS*ND];

// ---------------- helpers ----------------
__device__ __forceinline__ float to_tf32(float x) {
    uint32_t u;
    asm("cvt.rna.tf32.f32 %0, %1;" : "=r"(u) : "f"(x));
    return __uint_as_float(u);
}

__device__ __forceinline__ void mma_tf32(float c[4],
                                         uint32_t a0, uint32_t a1, uint32_t a2, uint32_t a3,
                                         uint32_t b0, uint32_t b1)
{
    asm volatile("mma.sync.aligned.m16n8k8.row.col.f32.tf32.tf32.f32 "
                 "{%0,%1,%2,%3}, {%4,%5,%6,%7}, {%8,%9}, {%0,%1,%2,%3};"
                 : "+f"(c[0]), "+f"(c[1]), "+f"(c[2]), "+f"(c[3])
                 : "r"(a0), "r"(a1), "r"(a2), "r"(a3), "r"(b0), "r"(b1));
}

// ---------------- prep: 4 small 256x256x256 products, smem-tiled ----------------
// t<3 : g_Weff[t] = Win_t @ Wt      (C[r,d] = sum_c Win[t*E+r,c] * Wt[c,d])
// t==3: g_Wcomb   = Wfc @ Wout
__global__ void prep_gemmAB(const float* __restrict__ Win,
                            const float* __restrict__ Wq, const float* __restrict__ Wk,
                            const float* __restrict__ Wv, const float* __restrict__ Wfc,
                            const float* __restrict__ Wout)
{
    __shared__ __align__(16) float As[16][68];   // [c][r]
    __shared__ __align__(16) float Bs[16][68];   // [c][d]
    const int tt = blockIdx.z;
    const float* A; const float* B; float* C;
    if (tt < 3) { A = Win + (size_t)tt*NE*NE; B = (tt==0)?Wq:(tt==1)?Wk:Wv; C = g_Weff + (size_t)tt*NE*ND; }
    else        { A = Wfc; B = Wout; C = g_Wcomb; }

    const int t   = threadIdx.x;
    const int m0  = blockIdx.y * 64;
    const int d0  = blockIdx.x * 64;
    const int lrow = t >> 2;          // 0..63
    const int lc4  = (t & 3) << 2;    // 0,4,8,12
    const int brow = t >> 4;          // 0..15
    const int bc4  = (t & 15) << 2;   // 0..60
    const int ty = t >> 4, tx = t & 15;

    float acc[4][4] = {};
    for (int k0 = 0; k0 < NE; k0 += 16) {
        float4 av = *(const float4*)&A[(size_t)(m0 + lrow)*NE + k0 + lc4];
        As[lc4+0][lrow] = av.x; As[lc4+1][lrow] = av.y;
        As[lc4+2][lrow] = av.z; As[lc4+3][lrow] = av.w;
        *(float4*)&Bs[brow][bc4] = *(const float4*)&B[(size_t)(k0 + brow)*NE + d0 + bc4];
        __syncthreads();
        #pragma unroll
        for (int kk = 0; kk < 16; kk++) {
            float4 a4 = *(const float4*)&As[kk][ty << 2];
            float4 b4 = *(const float4*)&Bs[kk][tx << 2];
            float ar[4] = {a4.x, a4.y, a4.z, a4.w};
            float br[4] = {b4.x, b4.y, b4.z, b4.w};
            #pragma unroll
            for (int i = 0; i < 4; i++)
                #pragma unroll
                for (int j = 0; j < 4; j++)
                    acc[i][j] += ar[i] * br[j];
        }
        __syncthreads();
    }
    #pragma unroll
    for (int i = 0; i < 4; i++) {
        float4 o = {acc[i][0], acc[i][1], acc[i][2], acc[i][3]};
        *(float4*)&C[(size_t)(m0 + (ty<<2) + i)*NE + d0 + (tx<<2)] = o;
    }
}

// ---------------- bias fold: warp per output ----------------
// j<768 : g_beff[j]  = bin_[j] + Win[j,:] . b_t      (t = j>>8)
// j>=768: g_bcomb[r] = bfc[r]  + Wfc[r,:] . bout
__global__ void bias_kernel(const float* __restrict__ Win, const float* __restrict__ bin_,
                            const float* __restrict__ bq, const float* __restrict__ bk,
                            const float* __restrict__ bv, const float* __restrict__ Wfc,
                            const float* __restrict__ bout, const float* __restrict__ bfc)
{
    int wid = blockIdx.x * 8 + (threadIdx.x >> 5);   // 0..1023
    int lane = threadIdx.x & 31;
    const float* row; const float* vec; float base;
    if (wid < 3*NE) {
        int t = wid >> 8;
        row = Win + (size_t)wid * NE;
        vec = (t == 0) ? bq : (t == 1) ? bk : bv;
        base = bin_[wid];
    } else {
        int r = wid - 3*NE;
        row = Wfc + (size_t)r * NE;
        vec = bout;
        base = bfc[r];
    }
    float s = 0.f;
    #pragma unroll
    for (int u = 0; u < 8; u++) s += row[u*32 + lane] * vec[u*32 + lane];
    #pragma unroll
    for (int o = 16; o >= 1; o >>= 1) s += __shfl_xor_sync(0xffffffffu, s, o);
    if (lane == 0) {
        if (wid < 3*NE) g_beff[wid] = base + s;
        else            g_bcomb[wid - 3*NE] = base + s;
    }
}

// ---------------- tensor-core GEMM: C[M,N] = A[M,K] @ W[N,K]^T + bias (+resid) ----------------
// tf32 mma.sync m16n8k8. Block tile 128x128, BK=32, 256 threads (8 warps: 2m x 4n),
// warp tile 64x32 (4 m16-tiles x 4 n8-tiles). M,N multiples of 128; K multiple of 32.
#define SMSTR 36
__global__ void __launch_bounds__(256) gemm_mma(const float* __restrict__ A,
                                                const float* __restrict__ W,
                                                const float* __restrict__ bias,
                                                const float* __restrict__ resid,
                                                float* __restrict__ C, int N, int K)
{
    __shared__ __align__(16) float As[128][SMSTR];
    __shared__ __align__(16) float Bs[128][SMSTR];
    const int tid = threadIdx.x;
    const int m0 = blockIdx.y * 128;
    const int n0 = blockIdx.x * 128;
    const int warp = tid >> 5;
    const int lane = tid & 31;
    const int wm = warp >> 2;       // 0..1
    const int wn = warp & 3;        // 0..3
    const int grp = lane >> 2;      // 0..7
    const int tig = lane & 3;       // 0..3

    const int ldr = tid >> 3;           // 0..31
    const int ldc = (tid & 7) << 2;     // 0..28

    float acc[4][4][4] = {};

    for (int k0 = 0; k0 < K; k0 += 32) {
        // global -> smem (with tf32 rounding)
        #pragma unroll
        for (int p = 0; p < 4; p++) {
            int row = ldr + p * 32;
            float4 av = *(const float4*)&A[(size_t)(m0 + row)*K + k0 + ldc];
            float4 wv = *(const float4*)&W[(size_t)(n0 + row)*K + k0 + ldc];
            float4 at = {to_tf32(av.x), to_tf32(av.y), to_tf32(av.z), to_tf32(av.w)};
            float4 wt = {to_tf32(wv.x), to_tf32(wv.y), to_tf32(wv.z), to_tf32(wv.w)};
            *(float4*)&As[row][ldc] = at;
            *(float4*)&Bs[row][ldc] = wt;
        }
        __syncthreads();
        #pragma unroll
        for (int kk = 0; kk < 32; kk += 8) {
            uint32_t af[4][4], bf[4][2];
            #pragma unroll
            for (int mt = 0; mt < 4; mt++) {
                int r = wm*64 + mt*16 + grp;
                af[mt][0] = __float_as_uint(As[r    ][kk + tig]);
                af[mt][1] = __float_as_uint(As[r + 8][kk + tig]);
                af[mt][2] = __float_as_uint(As[r    ][kk + 4 + tig]);
                af[mt][3] = __float_as_uint(As[r + 8][kk + 4 + tig]);
            }
            #pragma unroll
            for (int nt = 0; nt < 4; nt++) {
                int c = wn*32 + nt*8 + grp;
                bf[nt][0] = __float_as_uint(Bs[c][kk + tig]);
                bf[nt][1] = __float_as_uint(Bs[c][kk + 4 + tig]);
            }
            #pragma unroll
            for (int mt = 0; mt < 4; mt++)
                #pragma unroll
                for (int nt = 0; nt < 4; nt++)
                    mma_tf32(acc[mt][nt], af[mt][0], af[mt][1], af[mt][2], af[mt][3],
                             bf[nt][0], bf[nt][1]);
        }
        __syncthreads();
    }

    // epilogue
    #pragma unroll
    for (int mt = 0; mt < 4; mt++) {
        #pragma unroll
        for (int nt = 0; nt < 4; nt++) {
            int col = n0 + wn*32 + nt*8 + 2*tig;
            float bx = bias[col], by = bias[col + 1];
            int r0 = m0 + wm*64 + mt*16 + grp;
            float2 o0 = {acc[mt][nt][0] + bx, acc[mt][nt][1] + by};
            float2 o1 = {acc[mt][nt][2] + bx, acc[mt][nt][3] + by};
            if (resid) {
                float2 r0v = *(const float2*)&resid[(size_t)r0 * N + col];
                float2 r1v = *(const float2*)&resid[(size_t)(r0 + 8) * N + col];
                o0.x += r0v.x; o0.y += r0v.y;
                o1.x += r1v.x; o1.y += r1v.y;
            }
            *(float2*)&C[(size_t)r0 * N + col] = o0;
            *(float2*)&C[(size_t)(r0 + 8) * N + col] = o1;
        }
    }
}

// ---------------- banded attention ----------------
// grid: (SQ/QB, NB*NH), 256 threads (8 warps, 4 queries each). Warp-per-query, lane = head dim.
__global__ void attn_kernel(const int* __restrict__ reqp, float* __restrict__ ctx)
{
    __shared__ float sk[MAXW * HD];
    __shared__ float sv[MAXW * HD];
    const float* qkv = g_qkv;
    const int req = *reqp;
    const int bh = blockIdx.y;
    const int b = bh / NH;
    const int h = bh % NH;
    const int hoff = h * HD;
    const int q0 = blockIdx.x * QB;
    const int w0 = max(0, q0 - (req - 1));
    const int w1 = min(SQ - 1, q0 + QB - 1 + (req - 1));
    const int cw = w1 - w0 + 1;
    const bool stg = (cw <= MAXW);

    if (stg) {
        for (int e = threadIdx.x; e < cw * HD; e += blockDim.x) {
            int r = e >> 5, d = e & 31;
            size_t base = (size_t)((w0 + r) * NB + b) * LDQKV + hoff + d;
            sk[e] = qkv[base + NE];
            sv[e] = qkv[base + 2 * NE];
        }
        __syncthreads();
    }

    const int warp = threadIdx.x >> 5;
    const int lane = threadIdx.x & 31;
    const float scale = rsqrtf((float)HD);

    for (int tq = 0; tq < QB / 8; tq++) {
        int i = q0 + warp * (QB / 8) + tq;
        float qv = qkv[(size_t)(i * NB + b) * LDQKV + hoff + lane];
        int jlo = max(0, i - req + 1);
        int jhi = min(SQ - 1, i + req - 1);
        int cnt = jhi - jlo + 1;   // <= 2*req-1 (supports req<=64)

        float sc[4] = {-CUDART_INF_F, -CUDART_INF_F, -CUDART_INF_F, -CUDART_INF_F};
        for (int jj = 0; jj < cnt; jj++) {
            int j = jlo + jj;
            float kd = stg ? sk[(j - w0) * HD + lane]
                           : qkv[(size_t)(j * NB + b) * LDQKV + hoff + lane + NE];
            float p = qv * kd;
            p += __shfl_xor_sync(0xffffffffu, p, 16);
            p += __shfl_xor_sync(0xffffffffu, p, 8);
            p += __shfl_xor_sync(0xffffffffu, p, 4);
            p += __shfl_xor_sync(0xffffffffu, p, 2);
            p += __shfl_xor_sync(0xffffffffu, p, 1);
            if (lane == (jj & 31)) sc[jj >> 5] = p * scale;
        }

        float mx = fmaxf(fmaxf(sc[0], sc[1]), fmaxf(sc[2], sc[3]));
        mx = fmaxf(mx, __shfl_xor_sync(0xffffffffu, mx, 16));
        mx = fmaxf(mx, __shfl_xor_sync(0xffffffffu, mx, 8));
        mx = fmaxf(mx, __shfl_xor_sync(0xffffffffu, mx, 4));
        mx = fmaxf(mx, __shfl_xor_sync(0xffffffffu, mx, 2));
        mx = fmaxf(mx, __shfl_xor_sync(0xffffffffu, mx, 1));

        float p[4];
        float sum = 0.f;
        #pragma unroll
        for (int u = 0; u < 4; u++) {
            int jj = u * 32 + lane;
            p[u] = (jj < cnt) ? __expf(sc[u] - mx) : 0.f;
            sum += p[u];
        }
        sum += __shfl_xor_sync(0xffffffffu, sum, 16);
        sum += __shfl_xor_sync(0xffffffffu, sum, 8);
        sum += __shfl_xor_sync(0xffffffffu, sum, 4);
        sum += __shfl_xor_sync(0xffffffffu, sum, 2);
        sum += __shfl_xor_sync(0xffffffffu, sum, 1);

        float acc = 0.f;
        for (int jj = 0; jj < cnt; jj++) {
            float pj = __shfl_sync(0xffffffffu, p[jj >> 5], jj & 31);
            float vd = stg ? sv[(jlo - w0 + jj) * HD + lane]
                           : qkv[(size_t)((jlo + jj) * NB + b) * LDQKV + hoff + lane + 2 * NE];
            acc += pj * vd;
        }
        ctx[(size_t)(i * NB + b) * NE + hoff + lane] = acc / sum;
    }
}

// ---------------- layernorm (warp per row of 256) ----------------
__global__ void ln_kernel(const float* __restrict__ gamma, const float* __restrict__ beta,
                          float* __restrict__ out)
{
    int row = blockIdx.x * 8 + (threadIdx.x >> 5);
    int lane = threadIdx.x & 31;
    const float* yr = g_y + (size_t)row * ND;
    float v[8], s = 0.f, s2 = 0.f;
    #pragma unroll
    for (int u = 0; u < 8; u++) {
        v[u] = yr[u * 32 + lane];
        s += v[u];
        s2 += v[u] * v[u];
    }
    #pragma unroll
    for (int o = 16; o >= 1; o >>= 1) {
        s  += __shfl_xor_sync(0xffffffffu, s, o);
        s2 += __shfl_xor_sync(0xffffffffu, s2, o);
    }
    float mu  = s * (1.f / ND);
    float var = s2 * (1.f / ND) - mu * mu;
    float inv = rsqrtf(var + 1e-6f);
    #pragma unroll
    for (int u = 0; u < 8; u++) {
        int c = u * 32 + lane;
        out[(size_t)row * ND + c] = (v[u] - mu) * inv * gamma[c] + beta[c];
    }
}

// ---------------- launch ----------------
extern "C" void kernel_launch(void* const* d_in, const int* in_sizes, int n_in,
                              void* d_out, int out_size)
{
    const float* mod  = (const float*)d_in[0];
    // d_in[1] = mask (unused in this branch)
    const float* Wq   = (const float*)d_in[2];
    const float* bq   = (const float*)d_in[3];
    const float* Wk   = (const float*)d_in[4];
    const float* bk   = (const float*)d_in[5];
    const float* Wv   = (const float*)d_in[6];
    const float* bv   = (const float*)d_in[7];
    const float* Win  = (const float*)d_in[8];
    const float* bin_ = (const float*)d_in[9];
    const float* Wout = (const float*)d_in[10];
    const float* bout = (const float*)d_in[11];
    const float* Wfc  = (const float*)d_in[12];
    const float* bfc  = (const float*)d_in[13];
    const float* gamma= (const float*)d_in[14];
    const float* beta = (const float*)d_in[15];
    const int*   req  = (const int*)d_in[16];
    float* out = (float*)d_out;

    float *dWeff, *dbeff, *dWcomb, *dbcomb, *dqkv, *dctx, *dy;
    cudaGetSymbolAddress((void**)&dWeff,  g_Weff);
    cudaGetSymbolAddress((void**)&dbeff,  g_beff);
    cudaGetSymbolAddress((void**)&dWcomb, g_Wcomb);
    cudaGetSymbolAddress((void**)&dbcomb, g_bcomb);
    cudaGetSymbolAddress((void**)&dqkv,   g_qkv);
    cudaGetSymbolAddress((void**)&dctx,   g_ctx);
    cudaGetSymbolAddress((void**)&dy,     g_y);

    // 1. fold weights: (Win_t@Wt for t=q,k,v) and (Wfc@Wout), plus bias folds
    prep_gemmAB<<<dim3(4, 4, 4), 256>>>(Win, Wq, Wk, Wv, Wfc, Wout);
    bias_kernel<<<128, 256>>>(Win, bin_, bq, bk, bv, Wfc, bout, bfc);

    // 2. fused qkv projection: [8192,256] @ [768,256]^T   (tf32 tensor cores)
    gemm_mma<<<dim3(LDQKV / 128, MROWS / 128), 256>>>(mod, dWeff, dbeff, nullptr, dqkv, LDQKV, ND);

    // 3. banded attention
    attn_kernel<<<dim3(SQ / QB, NB * NH), 256>>>(req, dctx);

    // 4. fused out_proj+fc with residual: ctx @ (Wfc@Wout)^T + bcomb + mod
    gemm_mma<<<dim3(ND / 128, MROWS / 128), 256>>>(dctx, dWcomb, dbcomb, mod, dy, ND, NE);

    // 5. layernorm
    ln_kernel<<<MROWS / 8, 256>>>(gamma, beta, out);
}

// round 3
// speedup vs baseline: 1.5797x; 1.5495x over previous
#include <cuda_runtime.h>
#include <math_constants.h>
#include <cstdint>

#define SQ 2048
#define NB 4
#define ND 256
#define NE 256
#define NH 8
#define HD 32
#define MROWS (SQ*NB)       // 8192
#define LDQKV (3*NE)        // 768
#define QB 32
#define MAXW 160

// ---------------- scratch (device globals; no allocation) ----------------
__device__ float g_Weff[3*NE*ND];          // stacked (Win_q@Wq; Win_k@Wk; Win_v@Wv)  [768,256]
__device__ float g_beff[3*NE];
__device__ float g_Wcomb[ND*NE];           // Wfc @ Wout  [256,256]
__device__ float g_bcomb[ND];
__device__ float g_qkv[(size_t)MROWS*LDQKV];
__device__ float g_ctx[(size_t)MROWS*NE];
__device__ float g_y[(size_t)MROWS*ND];

// ---------------- helpers ----------------
__device__ __forceinline__ float to_tf32(float x) {
    uint32_t u;
    asm("cvt.rna.tf32.f32 %0, %1;" : "=r"(u) : "f"(x));
    return __uint_as_float(u);
}

__device__ __forceinline__ void mma_tf32(float c[4],
                                         uint32_t a0, uint32_t a1, uint32_t a2, uint32_t a3,
                                         uint32_t b0, uint32_t b1)
{
    asm volatile("mma.sync.aligned.m16n8k8.row.col.f32.tf32.tf32.f32 "
                 "{%0,%1,%2,%3}, {%4,%5,%6,%7}, {%8,%9}, {%0,%1,%2,%3};"
                 : "+f"(c[0]), "+f"(c[1]), "+f"(c[2]), "+f"(c[3])
                 : "r"(a0), "r"(a1), "r"(a2), "r"(a3), "r"(b0), "r"(b1));
}

// ---------------- prep: 4 small 256x256x256 products, smem-tiled ----------------
// t<3 : g_Weff[t] = Win_t @ Wt      (C[r,d] = sum_c Win[t*E+r,c] * Wt[c,d])
// t==3: g_Wcomb   = Wfc @ Wout
__global__ void prep_gemmAB(const float* __restrict__ Win,
                            const float* __restrict__ Wq, const float* __restrict__ Wk,
                            const float* __restrict__ Wv, const float* __restrict__ Wfc,
                            const float* __restrict__ Wout)
{
    __shared__ __align__(16) float As[16][68];   // [c][r]
    __shared__ __align__(16) float Bs[16][68];   // [c][d]
    const int tt = blockIdx.z;
    const float* A; const float* B; float* C;
    if (tt < 3) { A = Win + (size_t)tt*NE*NE; B = (tt==0)?Wq:(tt==1)?Wk:Wv; C = g_Weff + (size_t)tt*NE*ND; }
    else        { A = Wfc; B = Wout; C = g_Wcomb; }

    const int t   = threadIdx.x;
    const int m0  = blockIdx.y * 64;
    const int d0  = blockIdx.x * 64;
    const int lrow = t >> 2;          // 0..63
    const int lc4  = (t & 3) << 2;    // 0,4,8,12
    const int brow = t >> 4;          // 0..15
    const int bc4  = (t & 15) << 2;   // 0..60
    const int ty = t >> 4, tx = t & 15;

    float acc[4][4] = {};
    for (int k0 = 0; k0 < NE; k0 += 16) {
        float4 av = *(const float4*)&A[(size_t)(m0 + lrow)*NE + k0 + lc4];
        As[lc4+0][lrow] = av.x; As[lc4+1][lrow] = av.y;
        As[lc4+2][lrow] = av.z; As[lc4+3][lrow] = av.w;
        *(float4*)&Bs[brow][bc4] = *(const float4*)&B[(size_t)(k0 + brow)*NE + d0 + bc4];
        __syncthreads();
        #pragma unroll
        for (int kk = 0; kk < 16; kk++) {
            float4 a4 = *(const float4*)&As[kk][ty << 2];
            float4 b4 = *(const float4*)&Bs[kk][tx << 2];
            float ar[4] = {a4.x, a4.y, a4.z, a4.w};
            float br[4] = {b4.x, b4.y, b4.z, b4.w};
            #pragma unroll
            for (int i = 0; i < 4; i++)
                #pragma unroll
                for (int j = 0; j < 4; j++)
                    acc[i][j] += ar[i] * br[j];
        }
        __syncthreads();
    }
    #pragma unroll
    for (int i = 0; i < 4; i++) {
        float4 o = {acc[i][0], acc[i][1], acc[i][2], acc[i][3]};
        *(float4*)&C[(size_t)(m0 + (ty<<2) + i)*NE + d0 + (tx<<2)] = o;
    }
}

// ---------------- bias fold: warp per output ----------------
// j<768 : g_beff[j]  = bin_[j] + Win[j,:] . b_t      (t = j>>8)
// j>=768: g_bcomb[r] = bfc[r]  + Wfc[r,:] . bout
__global__ void bias_kernel(const float* __restrict__ Win, const float* __restrict__ bin_,
                            const float* __restrict__ bq, const float* __restrict__ bk,
                            const float* __restrict__ bv, const float* __restrict__ Wfc,
                            const float* __restrict__ bout, const float* __restrict__ bfc)
{
    int wid = blockIdx.x * 8 + (threadIdx.x >> 5);   // 0..1023
    int lane = threadIdx.x & 31;
    const float* row; const float* vec; float base;
    if (wid < 3*NE) {
        int t = wid >> 8;
        row = Win + (size_t)wid * NE;
        vec = (t == 0) ? bq : (t == 1) ? bk : bv;
        base = bin_[wid];
    } else {
        int r = wid - 3*NE;
        row = Wfc + (size_t)r * NE;
        vec = bout;
        base = bfc[r];
    }
    float s = 0.f;
    #pragma unroll
    for (int u = 0; u < 8; u++) s += row[u*32 + lane] * vec[u*32 + lane];
    #pragma unroll
    for (int o = 16; o >= 1; o >>= 1) s += __shfl_xor_sync(0xffffffffu, s, o);
    if (lane == 0) {
        if (wid < 3*NE) g_beff[wid] = base + s;
        else            g_bcomb[wid - 3*NE] = base + s;
    }
}

// ---------------- tensor-core GEMM: C[M,N] = A[M,K] @ W[N,K]^T + bias (+resid) ----------------
// tf32 mma.sync m16n8k8. Block tile 128x128, BK=32, 256 threads (8 warps: 2m x 4n),
// warp tile 64x32 (4 m16-tiles x 4 n8-tiles). M,N multiples of 128; K multiple of 32.
#define SMSTR 36
__global__ void __launch_bounds__(256) gemm_mma(const float* __restrict__ A,
                                                const float* __restrict__ W,
                                                const float* __restrict__ bias,
                                                const float* __restrict__ resid,
                                                float* __restrict__ C, int N, int K)
{
    __shared__ __align__(16) float As[128][SMSTR];
    __shared__ __align__(16) float Bs[128][SMSTR];
    const int tid = threadIdx.x;
    const int m0 = blockIdx.y * 128;
    const int n0 = blockIdx.x * 128;
    const int warp = tid >> 5;
    const int lane = tid & 31;
    const int wm = warp >> 2;       // 0..1
    const int wn = warp & 3;        // 0..3
    const int grp = lane >> 2;      // 0..7
    const int tig = lane & 3;       // 0..3

    const int ldr = tid >> 3;           // 0..31
    const int ldc = (tid & 7) << 2;     // 0..28

    float acc[4][4][4] = {};

    for (int k0 = 0; k0 < K; k0 += 32) {
        // global -> smem (with tf32 rounding)
        #pragma unroll
        for (int p = 0; p < 4; p++) {
            int row = ldr + p * 32;
            float4 av = *(const float4*)&A[(size_t)(m0 + row)*K + k0 + ldc];
            float4 wv = *(const float4*)&W[(size_t)(n0 + row)*K + k0 + ldc];
            float4 at = {to_tf32(av.x), to_tf32(av.y), to_tf32(av.z), to_tf32(av.w)};
            float4 wt = {to_tf32(wv.x), to_tf32(wv.y), to_tf32(wv.z), to_tf32(wv.w)};
            *(float4*)&As[row][ldc] = at;
            *(float4*)&Bs[row][ldc] = wt;
        }
        __syncthreads();
        #pragma unroll
        for (int kk = 0; kk < 32; kk += 8) {
            uint32_t af[4][4], bf[4][2];
            #pragma unroll
            for (int mt = 0; mt < 4; mt++) {
                int r = wm*64 + mt*16 + grp;
                af[mt][0] = __float_as_uint(As[r    ][kk + tig]);
                af[mt][1] = __float_as_uint(As[r + 8][kk + tig]);
                af[mt][2] = __float_as_uint(As[r    ][kk + 4 + tig]);
                af[mt][3] = __float_as_uint(As[r + 8][kk + 4 + tig]);
            }
            #pragma unroll
            for (int nt = 0; nt < 4; nt++) {
                int c = wn*32 + nt*8 + grp;
                bf[nt][0] = __float_as_uint(Bs[c][kk + tig]);
                bf[nt][1] = __float_as_uint(Bs[c][kk + 4 + tig]);
            }
            #pragma unroll
            for (int mt = 0; mt < 4; mt++)
                #pragma unroll
                for (int nt = 0; nt < 4; nt++)
                    mma_tf32(acc[mt][nt], af[mt][0], af[mt][1], af[mt][2], af[mt][3],
                             bf[nt][0], bf[nt][1]);
        }
        __syncthreads();
    }

    // epilogue
    #pragma unroll
    for (int mt = 0; mt < 4; mt++) {
        #pragma unroll
        for (int nt = 0; nt < 4; nt++) {
            int col = n0 + wn*32 + nt*8 + 2*tig;
            float bx = bias[col], by = bias[col + 1];
            int r0 = m0 + wm*64 + mt*16 + grp;
            float2 o0 = {acc[mt][nt][0] + bx, acc[mt][nt][1] + by};
            float2 o1 = {acc[mt][nt][2] + bx, acc[mt][nt][3] + by};
            if (resid) {
                float2 r0v = *(const float2*)&resid[(size_t)r0 * N + col];
                float2 r1v = *(const float2*)&resid[(size_t)(r0 + 8) * N + col];
                o0.x += r0v.x; o0.y += r0v.y;
                o1.x += r1v.x; o1.y += r1v.y;
            }
            *(float2*)&C[(size_t)r0 * N + col] = o0;
            *(float2*)&C[(size_t)(r0 + 8) * N + col] = o1;
        }
    }
}

// ---------------- banded attention ----------------
// grid: (SQ/QB, NB*NH), 256 threads (8 warps, 4 queries each). Warp-per-query, lane = head dim.
__global__ void attn_kernel(const int* __restrict__ reqp, float* __restrict__ ctx)
{
    __shared__ float sk[MAXW * HD];
    __shared__ float sv[MAXW * HD];
    const float* qkv = g_qkv;
    const int req = *reqp;
    const int bh = blockIdx.y;
    const int b = bh / NH;
    const int h = bh % NH;
    const int hoff = h * HD;
    const int q0 = blockIdx.x * QB;
    const int w0 = max(0, q0 - (req - 1));
    const int w1 = min(SQ - 1, q0 + QB - 1 + (req - 1));
    const int cw = w1 - w0 + 1;
    const bool stg = (cw <= MAXW);

    if (stg) {
        for (int e = threadIdx.x; e < cw * HD; e += blockDim.x) {
            int r = e >> 5, d = e & 31;
            size_t base = (size_t)((w0 + r) * NB + b) * LDQKV + hoff + d;
            sk[e] = qkv[base + NE];
            sv[e] = qkv[base + 2 * NE];
        }
        __syncthreads();
    }

    const int warp = threadIdx.x >> 5;
    const int lane = threadIdx.x & 31;
    const float scale = rsqrtf((float)HD);

    for (int tq = 0; tq < QB / 8; tq++) {
        int i = q0 + warp * (QB / 8) + tq;
        float qv = qkv[(size_t)(i * NB + b) * LDQKV + hoff + lane];
        int jlo = max(0, i - req + 1);
        int jhi = min(SQ - 1, i + req - 1);
        int cnt = jhi - jlo + 1;   // <= 2*req-1 (supports req<=64)

        float sc[4] = {-CUDART_INF_F, -CUDART_INF_F, -CUDART_INF_F, -CUDART_INF_F};
        for (int jj = 0; jj < cnt; jj++) {
            int j = jlo + jj;
            float kd = stg ? sk[(j - w0) * HD + lane]
                           : qkv[(size_t)(j * NB + b) * LDQKV + hoff + lane + NE];
            float p = qv * kd;
            p += __shfl_xor_sync(0xffffffffu, p, 16);
            p += __shfl_xor_sync(0xffffffffu, p, 8);
            p += __shfl_xor_sync(0xffffffffu, p, 4);
            p += __shfl_xor_sync(0xffffffffu, p, 2);
            p += __shfl_xor_sync(0xffffffffu, p, 1);
            if (lane == (jj & 31)) sc[jj >> 5] = p * scale;
        }

        float mx = fmaxf(fmaxf(sc[0], sc[1]), fmaxf(sc[2], sc[3]));
        mx = fmaxf(mx, __shfl_xor_sync(0xffffffffu, mx, 16));
        mx = fmaxf(mx, __shfl_xor_sync(0xffffffffu, mx, 8));
        mx = fmaxf(mx, __shfl_xor_sync(0xffffffffu, mx, 4));
        mx = fmaxf(mx, __shfl_xor_sync(0xffffffffu, mx, 2));
        mx = fmaxf(mx, __shfl_xor_sync(0xffffffffu, mx, 1));

        float p[4];
        float sum = 0.f;
        #pragma unroll
        for (int u = 0; u < 4; u++) {
            int jj = u * 32 + lane;
            p[u] = (jj < cnt) ? __expf(sc[u] - mx) : 0.f;
            sum += p[u];
        }
        sum += __shfl_xor_sync(0xffffffffu, sum, 16);
        sum += __shfl_xor_sync(0xffffffffu, sum, 8);
        sum += __shfl_xor_sync(0xffffffffu, sum, 4);
        sum += __shfl_xor_sync(0xffffffffu, sum, 2);
        sum += __shfl_xor_sync(0xffffffffu, sum, 1);

        float acc = 0.f;
        for (int jj = 0; jj < cnt; jj++) {
            float pj = __shfl_sync(0xffffffffu, p[jj >> 5], jj & 31);
            float vd = stg ? sv[(jlo - w0 + jj) * HD + lane]
                           : qkv[(size_t)((jlo + jj) * NB + b) * LDQKV + hoff + lane + 2 * NE];
            acc += pj * vd;
        }
        ctx[(size_t)(i * NB + b) * NE + hoff + lane] = acc / sum;
    }
}

// ---------------- layernorm (warp per row of 256) ----------------
__global__ void ln_kernel(const float* __restrict__ gamma, const float* __restrict__ beta,
                          float* __restrict__ out)
{
    int row = blockIdx.x * 8 + (threadIdx.x >> 5);
    int lane = threadIdx.x & 31;
    const float* yr = g_y + (size_t)row * ND;
    float v[8], s = 0.f, s2 = 0.f;
    #pragma unroll
    for (int u = 0; u < 8; u++) {
        v[u] = yr[u * 32 + lane];
        s += v[u];
        s2 += v[u] * v[u];
    }
    #pragma unroll
    for (int o = 16; o >= 1; o >>= 1) {
        s  += __shfl_xor_sync(0xffffffffu, s, o);
        s2 += __shfl_xor_sync(0xffffffffu, s2, o);
    }
    float mu  = s * (1.f / ND);
    float var = s2 * (1.f / ND) - mu * mu;
    float inv = rsqrtf(var + 1e-6f);
    #pragma unroll
    for (int u = 0; u < 8; u++) {
        int c = u * 32 + lane;
        out[(size_t)row * ND + c] = (v[u] - mu) * inv * gamma[c] + beta[c];
    }
}

// ---------------- launch ----------------
extern "C" void kernel_launch(void* const* d_in, const int* in_sizes, int n_in,
                              void* d_out, int out_size)
{
    const float* mod  = (const float*)d_in[0];
    // d_in[1] = mask (unused in this branch)
    const float* Wq   = (const float*)d_in[2];
    const float* bq   = (const float*)d_in[3];
    const float* Wk   = (const float*)d_in[4];
    const float* bk   = (const float*)d_in[5];
    const float* Wv   = (const float*)d_in[6];
    const float* bv   = (const float*)d_in[7];
    const float* Win  = (const float*)d_in[8];
    const float* bin_ = (const float*)d_in[9];
    const float* Wout = (const float*)d_in[10];
    const float* bout = (const float*)d_in[11];
    const float* Wfc  = (const float*)d_in[12];
    const float* bfc  = (const float*)d_in[13];
    const float* gamma= (const float*)d_in[14];
    const float* beta = (const float*)d_in[15];
    const int*   req  = (const int*)d_in[16];
    float* out = (float*)d_out;

    float *dWeff, *dbeff, *dWcomb, *dbcomb, *dqkv, *dctx, *dy;
    cudaGetSymbolAddress((void**)&dWeff,  g_Weff);
    cudaGetSymbolAddress((void**)&dbeff,  g_beff);
    cudaGetSymbolAddress((void**)&dWcomb, g_Wcomb);
    cudaGetSymbolAddress((void**)&dbcomb, g_bcomb);
    cudaGetSymbolAddress((void**)&dqkv,   g_qkv);
    cudaGetSymbolAddress((void**)&dctx,   g_ctx);
    cudaGetSymbolAddress((void**)&dy,     g_y);

    // 1. fold weights: (Win_t@Wt for t=q,k,v) and (Wfc@Wout), plus bias folds
    prep_gemmAB<<<dim3(4, 4, 4), 256>>>(Win, Wq, Wk, Wv, Wfc, Wout);
    bias_kernel<<<128, 256>>>(Win, bin_, bq, bk, bv, Wfc, bout, bfc);

    // 2. fused qkv projection: [8192,256] @ [768,256]^T   (tf32 tensor cores)
    gemm_mma<<<dim3(LDQKV / 128, MROWS / 128), 256>>>(mod, dWeff, dbeff, nullptr, dqkv, LDQKV, ND);

    // 3. banded attention
    attn_kernel<<<dim3(SQ / QB, NB * NH), 256>>>(req, dctx);

    // 4. fused out_proj+fc with residual: ctx @ (Wfc@Wout)^T + bcomb + mod
    gemm_mma<<<dim3(ND / 128, MROWS / 128), 256>>>(dctx, dWcomb, dbcomb, mod, dy, ND, NE);

    // 5. layernorm
    ln_kernel<<<MROWS / 8, 256>>>(gamma, beta, out);
}

// round 4
// speedup vs baseline: 3.8486x; 2.4363x over previous
#include <cuda_runtime.h>
#include <math_constants.h>
#include <cstdint>

#define SQ 2048
#define NB 4
#define ND 256
#define NE 256
#define NH 8
#define HD 32
#define MROWS (SQ*NB)       // 8192
#define LDQKV (3*NE)        // 768

// ---------------- scratch (device globals; no allocation) ----------------
__device__ float g_Weff[3*NE*ND];          // stacked (Win_q@Wq; Win_k@Wk; Win_v@Wv)  [768,256]
__device__ float g_beff[3*NE];
__device__ float g_Wcomb[ND*NE];           // Wfc @ Wout  [256,256]
__device__ float g_bcomb[ND];
__device__ float g_qkv[(size_t)MROWS*LDQKV];
__device__ float g_ctx[(size_t)MROWS*NE];
__device__ float g_y[(size_t)MROWS*ND];

// ---------------- helpers ----------------
__device__ __forceinline__ float to_tf32(float x) {
    uint32_t u;
    asm("cvt.rna.tf32.f32 %0, %1;" : "=r"(u) : "f"(x));
    return __uint_as_float(u);
}

__device__ __forceinline__ void mma_tf32(float c[4],
                                         uint32_t a0, uint32_t a1, uint32_t a2, uint32_t a3,
                                         uint32_t b0, uint32_t b1)
{
    asm volatile("mma.sync.aligned.m16n8k8.row.col.f32.tf32.tf32.f32 "
                 "{%0,%1,%2,%3}, {%4,%5,%6,%7}, {%8,%9}, {%0,%1,%2,%3};"
                 : "+f"(c[0]), "+f"(c[1]), "+f"(c[2]), "+f"(c[3])
                 : "r"(a0), "r"(a1), "r"(a2), "r"(a3), "r"(b0), "r"(b1));
}

// ---------------- prep: 4 small 256x256x256 products, smem-tiled ----------------
__global__ void prep_gemmAB(const float* __restrict__ Win,
                            const float* __restrict__ Wq, const float* __restrict__ Wk,
                            const float* __restrict__ Wv, const float* __restrict__ Wfc,
                            const float* __restrict__ Wout)
{
    __shared__ __align__(16) float As[16][68];   // [c][r]
    __shared__ __align__(16) float Bs[16][68];   // [c][d]
    const int tt = blockIdx.z;
    const float* A; const float* B; float* C;
    if (tt < 3) { A = Win + (size_t)tt*NE*NE; B = (tt==0)?Wq:(tt==1)?Wk:Wv; C = g_Weff + (size_t)tt*NE*ND; }
    else        { A = Wfc; B = Wout; C = g_Wcomb; }

    const int t   = threadIdx.x;
    const int m0  = blockIdx.y * 64;
    const int d0  = blockIdx.x * 64;
    const int lrow = t >> 2;
    const int lc4  = (t & 3) << 2;
    const int brow = t >> 4;
    const int bc4  = (t & 15) << 2;
    const int ty = t >> 4, tx = t & 15;

    float acc[4][4] = {};
    for (int k0 = 0; k0 < NE; k0 += 16) {
        float4 av = *(const float4*)&A[(size_t)(m0 + lrow)*NE + k0 + lc4];
        As[lc4+0][lrow] = av.x; As[lc4+1][lrow] = av.y;
        As[lc4+2][lrow] = av.z; As[lc4+3][lrow] = av.w;
        *(float4*)&Bs[brow][bc4] = *(const float4*)&B[(size_t)(k0 + brow)*NE + d0 + bc4];
        __syncthreads();
        #pragma unroll
        for (int kk = 0; kk < 16; kk++) {
            float4 a4 = *(const float4*)&As[kk][ty << 2];
            float4 b4 = *(const float4*)&Bs[kk][tx << 2];
            float ar[4] = {a4.x, a4.y, a4.z, a4.w};
            float br[4] = {b4.x, b4.y, b4.z, b4.w};
            #pragma unroll
            for (int i = 0; i < 4; i++)
                #pragma unroll
                for (int j = 0; j < 4; j++)
                    acc[i][j] += ar[i] * br[j];
        }
        __syncthreads();
    }
    #pragma unroll
    for (int i = 0; i < 4; i++) {
        float4 o = {acc[i][0], acc[i][1], acc[i][2], acc[i][3]};
        *(float4*)&C[(size_t)(m0 + (ty<<2) + i)*NE + d0 + (tx<<2)] = o;
    }
}

// ---------------- bias fold: warp per output ----------------
__global__ void bias_kernel(const float* __restrict__ Win, const float* __restrict__ bin_,
                            const float* __restrict__ bq, const float* __restrict__ bk,
                            const float* __restrict__ bv, const float* __restrict__ Wfc,
                            const float* __restrict__ bout, const float* __restrict__ bfc)
{
    int wid = blockIdx.x * 8 + (threadIdx.x >> 5);   // 0..1023
    int lane = threadIdx.x & 31;
    const float* row; const float* vec; float base;
    if (wid < 3*NE) {
        int t = wid >> 8;
        row = Win + (size_t)wid * NE;
        vec = (t == 0) ? bq : (t == 1) ? bk : bv;
        base = bin_[wid];
    } else {
        int r = wid - 3*NE;
        row = Wfc + (size_t)r * NE;
        vec = bout;
        base = bfc[r];
    }
    float s = 0.f;
    #pragma unroll
    for (int u = 0; u < 8; u++) s += row[u*32 + lane] * vec[u*32 + lane];
    #pragma unroll
    for (int o = 16; o >= 1; o >>= 1) s += __shfl_xor_sync(0xffffffffu, s, o);
    if (lane == 0) {
        if (wid < 3*NE) g_beff[wid] = base + s;
        else            g_bcomb[wid - 3*NE] = base + s;
    }
}

// ---------------- tensor-core GEMM: C[M,N] = A[M,K] @ W[N,K]^T + bias (+resid) ----------------
#define SMSTR 36
__global__ void __launch_bounds__(256) gemm_mma(const float* __restrict__ A,
                                                const float* __restrict__ W,
                                                const float* __restrict__ bias,
                                                const float* __restrict__ resid,
                                                float* __restrict__ C, int N, int K)
{
    __shared__ __align__(16) float As[128][SMSTR];
    __shared__ __align__(16) float Bs[128][SMSTR];
    const int tid = threadIdx.x;
    const int m0 = blockIdx.y * 128;
    const int n0 = blockIdx.x * 128;
    const int warp = tid >> 5;
    const int lane = tid & 31;
    const int wm = warp >> 2;
    const int wn = warp & 3;
    const int grp = lane >> 2;
    const int tig = lane & 3;

    const int ldr = tid >> 3;
    const int ldc = (tid & 7) << 2;

    float acc[4][4][4] = {};

    for (int k0 = 0; k0 < K; k0 += 32) {
        #pragma unroll
        for (int p = 0; p < 4; p++) {
            int row = ldr + p * 32;
            float4 av = *(const float4*)&A[(size_t)(m0 + row)*K + k0 + ldc];
            float4 wv = *(const float4*)&W[(size_t)(n0 + row)*K + k0 + ldc];
            float4 at = {to_tf32(av.x), to_tf32(av.y), to_tf32(av.z), to_tf32(av.w)};
            float4 wt = {to_tf32(wv.x), to_tf32(wv.y), to_tf32(wv.z), to_tf32(wv.w)};
            *(float4*)&As[row][ldc] = at;
            *(float4*)&Bs[row][ldc] = wt;
        }
        __syncthreads();
        #pragma unroll
        for (int kk = 0; kk < 32; kk += 8) {
            uint32_t af[4][4], bf[4][2];
            #pragma unroll
            for (int mt = 0; mt < 4; mt++) {
                int r = wm*64 + mt*16 + grp;
                af[mt][0] = __float_as_uint(As[r    ][kk + tig]);
                af[mt][1] = __float_as_uint(As[r + 8][kk + tig]);
                af[mt][2] = __float_as_uint(As[r    ][kk + 4 + tig]);
                af[mt][3] = __float_as_uint(As[r + 8][kk + 4 + tig]);
            }
            #pragma unroll
            for (int nt = 0; nt < 4; nt++) {
                int c = wn*32 + nt*8 + grp;
                bf[nt][0] = __float_as_uint(Bs[c][kk + tig]);
                bf[nt][1] = __float_as_uint(Bs[c][kk + 4 + tig]);
            }
            #pragma unroll
            for (int mt = 0; mt < 4; mt++)
                #pragma unroll
                for (int nt = 0; nt < 4; nt++)
                    mma_tf32(acc[mt][nt], af[mt][0], af[mt][1], af[mt][2], af[mt][3],
                             bf[nt][0], bf[nt][1]);
        }
        __syncthreads();
    }

    #pragma unroll
    for (int mt = 0; mt < 4; mt++) {
        #pragma unroll
        for (int nt = 0; nt < 4; nt++) {
            int col = n0 + wn*32 + nt*8 + 2*tig;
            float bx = bias[col], by = bias[col + 1];
            int r0 = m0 + wm*64 + mt*16 + grp;
            float2 o0 = {acc[mt][nt][0] + bx, acc[mt][nt][1] + by};
            float2 o1 = {acc[mt][nt][2] + bx, acc[mt][nt][3] + by};
            if (resid) {
                float2 r0v = *(const float2*)&resid[(size_t)r0 * N + col];
                float2 r1v = *(const float2*)&resid[(size_t)(r0 + 8) * N + col];
                o0.x += r0v.x; o0.y += r0v.y;
                o1.x += r1v.x; o1.y += r1v.y;
            }
            *(float2*)&C[(size_t)r0 * N + col] = o0;
            *(float2*)&C[(size_t)(r0 + 8) * N + col] = o1;
        }
    }
}

// ---------------- banded attention via tensor cores ----------------
// Block: 64 queries x one (b,h), 2 warps (each warp owns 32 queries).
// Per warp: scores S[32x64] = Q[32x32] @ K^T (64-key window), masked softmax in
// registers, ctx C[32x32] = P[32x64] @ V. Supports req <= 17 (window 32+2*16=64).
// smem strides chosen so mma fragment LDS are conflict-free (bank = 4*grp+tig).
#define KST 36    // sK row stride
#define VST 100   // sVT row stride
#define QST 36    // sQ row stride
#define PST 68    // sP row stride
__global__ void __launch_bounds__(64) attn_mma(const int* __restrict__ reqp,
                                               float* __restrict__ ctx)
{
    __shared__ float sK[96*KST];       // keys [wbase..wbase+96) x 32 dims
    __shared__ float sVT[32*VST];      // dims x 96 keys (transposed V)
    __shared__ float sU[4352];         // union: Q[64][36] then P[w][32][68]

    const float* qkv = g_qkv;
    const int req = *reqp;
    const int bh = blockIdx.y;
    const int b = bh >> 3;
    const int hoff = (bh & 7) * HD;
    const int q0 = blockIdx.x * 64;
    const int wbase = q0 - (req - 1);

    const int tid = threadIdx.x;
    const int w = tid >> 5;
    const int lane = tid & 31;
    const int grp = lane >> 2;
    const int tig = lane & 3;
    const float scale = rsqrtf((float)HD);

    // ---- stage Q (scaled, tf32), K (tf32, zero-pad OOR), V^T ----
    #pragma unroll
    for (int u = tid; u < 512; u += 64) {            // Q: 64 rows x 8 float4
        int r = u >> 3, c4 = (u & 7) << 2;
        float4 v = *(const float4*)&qkv[(size_t)((q0 + r)*NB + b)*LDQKV + hoff + c4];
        sU[r*QST + c4 + 0] = to_tf32(v.x * scale);
        sU[r*QST + c4 + 1] = to_tf32(v.y * scale);
        sU[r*QST + c4 + 2] = to_tf32(v.z * scale);
        sU[r*QST + c4 + 3] = to_tf32(v.w * scale);
    }
    #pragma unroll
    for (int u = tid; u < 768; u += 64) {            // K + V: 96 rows x 8 float4
        int r = u >> 3, c4 = (u & 7) << 2;
        int key = wbase + r;
        float4 kv = {0.f, 0.f, 0.f, 0.f}, vv = {0.f, 0.f, 0.f, 0.f};
        if (key >= 0 && key < SQ) {
            size_t base = (size_t)(key*NB + b)*LDQKV + hoff + c4;
            kv = *(const float4*)&qkv[base + NE];
            vv = *(const float4*)&qkv[base + 2*NE];
        }
        sK[r*KST + c4 + 0] = to_tf32(kv.x);
        sK[r*KST + c4 + 1] = to_tf32(kv.y);
        sK[r*KST + c4 + 2] = to_tf32(kv.z);
        sK[r*KST + c4 + 3] = to_tf32(kv.w);
        sVT[(c4+0)*VST + r] = vv.x;
        sVT[(c4+1)*VST + r] = vv.y;
        sVT[(c4+2)*VST + r] = vv.z;
        sVT[(c4+3)*VST + r] = vv.w;
    }
    __syncthreads();

    // ---- scores: S[32x64] = Q @ K^T ----
    float sc[2][8][4] = {};
    #pragma unroll
    for (int ks = 0; ks < 4; ks++) {
        int kk = ks * 8;
        uint32_t af[2][4], bf[8][2];
        #pragma unroll
        for (int mt = 0; mt < 2; mt++) {
            int r = (w*32 + mt*16 + grp) * QST;
            af[mt][0] = __float_as_uint(sU[r + kk + tig]);
            af[mt][1] = __float_as_uint(sU[r + 8*QST + kk + tig]);
            af[mt][2] = __float_as_uint(sU[r + kk + 4 + tig]);
            af[mt][3] = __float_as_uint(sU[r + 8*QST + kk + 4 + tig]);
        }
        #pragma unroll
        for (int nt = 0; nt < 8; nt++) {
            int r = (w*32 + nt*8 + grp) * KST;
            bf[nt][0] = __float_as_uint(sK[r + kk + tig]);
            bf[nt][1] = __float_as_uint(sK[r + kk + 4 + tig]);
        }
        #pragma unroll
        for (int mt = 0; mt < 2; mt++)
            #pragma unroll
            for (int nt = 0; nt < 8; nt++)
                mma_tf32(sc[mt][nt], af[mt][0], af[mt][1], af[mt][2], af[mt][3],
                         bf[nt][0], bf[nt][1]);
    }

    // ---- mask + softmax (registers) ----
    const int iw = q0 + w*32;
    const int jw = wbase + w*32;
    float mx0[2] = {-CUDART_INF_F, -CUDART_INF_F};
    float mx1[2] = {-CUDART_INF_F, -CUDART_INF_F};
    #pragma unroll
    for (int mt = 0; mt < 2; mt++) {
        int i0 = iw + mt*16 + grp;
        int i1 = i0 + 8;
        #pragma unroll
        for (int nt = 0; nt < 8; nt++) {
            int j0 = jw + nt*8 + 2*tig;
            int j1 = j0 + 1;
            bool g0 = (j0 >= 0) & (j0 < SQ);
            bool g1 = (j1 >= 0) & (j1 < SQ);
            float* c = sc[mt][nt];
            c[0] = (g0 && abs(i0 - j0) < req) ? c[0] : -CUDART_INF_F;
            c[1] = (g1 && abs(i0 - j1) < req) ? c[1] : -CUDART_INF_F;
            c[2] = (g0 && abs(i1 - j0) < req) ? c[2] : -CUDART_INF_F;
            c[3] = (g1 && abs(i1 - j1) < req) ? c[3] : -CUDART_INF_F;
            mx0[mt] = fmaxf(mx0[mt], fmaxf(c[0], c[1]));
            mx1[mt] = fmaxf(mx1[mt], fmaxf(c[2], c[3]));
        }
    }
    #pragma unroll
    for (int o = 1; o <= 2; o <<= 1) {
        #pragma unroll
        for (int mt = 0; mt < 2; mt++) {
            mx0[mt] = fmaxf(mx0[mt], __shfl_xor_sync(0xffffffffu, mx0[mt], o));
            mx1[mt] = fmaxf(mx1[mt], __shfl_xor_sync(0xffffffffu, mx1[mt], o));
        }
    }
    float s0[2] = {0.f, 0.f}, s1[2] = {0.f, 0.f};
    #pragma unroll
    for (int mt = 0; mt < 2; mt++) {
        #pragma unroll
        for (int nt = 0; nt < 8; nt++) {
            float* c = sc[mt][nt];
            c[0] = __expf(c[0] - mx0[mt]);
            c[1] = __expf(c[1] - mx0[mt]);
            c[2] = __expf(c[2] - mx1[mt]);
            c[3] = __expf(c[3] - mx1[mt]);
            s0[mt] += c[0] + c[1];
            s1[mt] += c[2] + c[3];
        }
    }
    #pragma unroll
    for (int o = 1; o <= 2; o <<= 1) {
        #pragma unroll
        for (int mt = 0; mt < 2; mt++) {
            s0[mt] += __shfl_xor_sync(0xffffffffu, s0[mt], o);
            s1[mt] += __shfl_xor_sync(0xffffffffu, s1[mt], o);
        }
    }
    float rs0[2] = {1.f / s0[0], 1.f / s0[1]};
    float rs1[2] = {1.f / s1[0], 1.f / s1[1]};

    // ---- store P (tf32) into union region (overwrites Q) ----
    __syncthreads();   // all warps done reading sQ
    float* sP = sU + w * (32*PST);
    #pragma unroll
    for (int mt = 0; mt < 2; mt++) {
        #pragma unroll
        for (int nt = 0; nt < 8; nt++) {
            float* c = sc[mt][nt];
            int r0 = (mt*16 + grp) * PST + nt*8 + 2*tig;
            sP[r0          ] = to_tf32(c[0]);
            sP[r0 + 1      ] = to_tf32(c[1]);
            sP[r0 + 8*PST  ] = to_tf32(c[2]);
            sP[r0 + 8*PST+1] = to_tf32(c[3]);
        }
    }
    __syncwarp();

    // ---- ctx: C[32x32] = P[32x64] @ V[64x32] ----
    float ao[2][4][4] = {};
    #pragma unroll
    for (int ks = 0; ks < 8; ks++) {
        int kk = ks * 8;
        uint32_t af[2][4], bf[4][2];
        #pragma unroll
        for (int mt = 0; mt < 2; mt++) {
            int r = (mt*16 + grp) * PST;
            af[mt][0] = __float_as_uint(sP[r + kk + tig]);
            af[mt][1] = __float_as_uint(sP[r + 8*PST + kk + tig]);
            af[mt][2] = __float_as_uint(sP[r + kk + 4 + tig]);
            af[mt][3] = __float_as_uint(sP[r + 8*PST + kk + 4 + tig]);
        }
        #pragma unroll
        for (int nt = 0; nt < 4; nt++) {
            int r = (nt*8 + grp) * VST + w*32;
            bf[nt][0] = __float_as_uint(sVT[r + kk + tig]);
            bf[nt][1] = __float_as_uint(sVT[r + kk + 4 + tig]);
        }
        #pragma unroll
        for (int mt = 0; mt < 2; mt++)
            #pragma unroll
            for (int nt = 0; nt < 4; nt++)
                mma_tf32(ao[mt][nt], af[mt][0], af[mt][1], af[mt][2], af[mt][3],
                         bf[nt][0], bf[nt][1]);
    }

    // ---- epilogue: divide by row sums, write ctx ----
    #pragma unroll
    for (int mt = 0; mt < 2; mt++) {
        int i0 = iw + mt*16 + grp;
        #pragma unroll
        for (int nt = 0; nt < 4; nt++) {
            int dcol = hoff + nt*8 + 2*tig;
            float2 o0 = {ao[mt][nt][0] * rs0[mt], ao[mt][nt][1] * rs0[mt]};
            float2 o1 = {ao[mt][nt][2] * rs1[mt], ao[mt][nt][3] * rs1[mt]};
            *(float2*)&ctx[(size_t)(i0*NB + b)*NE + dcol] = o0;
            *(float2*)&ctx[(size_t)((i0 + 8)*NB + b)*NE + dcol] = o1;
        }
    }
}

// ---------------- layernorm (warp per row of 256) ----------------
__global__ void ln_kernel(const float* __restrict__ gamma, const float* __restrict__ beta,
                          float* __restrict__ out)
{
    int row = blockIdx.x * 8 + (threadIdx.x >> 5);
    int lane = threadIdx.x & 31;
    const float* yr = g_y + (size_t)row * ND;
    float v[8], s = 0.f, s2 = 0.f;
    #pragma unroll
    for (int u = 0; u < 8; u++) {
        v[u] = yr[u * 32 + lane];
        s += v[u];
        s2 += v[u] * v[u];
    }
    #pragma unroll
    for (int o = 16; o >= 1; o >>= 1) {
        s  += __shfl_xor_sync(0xffffffffu, s, o);
        s2 += __shfl_xor_sync(0xffffffffu, s2, o);
    }
    float mu  = s * (1.f / ND);
    float var = s2 * (1.f / ND) - mu * mu;
    float inv = rsqrtf(var + 1e-6f);
    #pragma unroll
    for (int u = 0; u < 8; u++) {
        int c = u * 32 + lane;
        out[(size_t)row * ND + c] = (v[u] - mu) * inv * gamma[c] + beta[c];
    }
}

// ---------------- launch ----------------
extern "C" void kernel_launch(void* const* d_in, const int* in_sizes, int n_in,
                              void* d_out, int out_size)
{
    const float* mod  = (const float*)d_in[0];
    const float* Wq   = (const float*)d_in[2];
    const float* bq   = (const float*)d_in[3];
    const float* Wk   = (const float*)d_in[4];
    const float* bk   = (const float*)d_in[5];
    const float* Wv   = (const float*)d_in[6];
    const float* bv   = (const float*)d_in[7];
    const float* Win  = (const float*)d_in[8];
    const float* bin_ = (const float*)d_in[9];
    const float* Wout = (const float*)d_in[10];
    const float* bout = (const float*)d_in[11];
    const float* Wfc  = (const float*)d_in[12];
    const float* bfc  = (const float*)d_in[13];
    const float* gamma= (const float*)d_in[14];
    const float* beta = (const float*)d_in[15];
    const int*   req  = (const int*)d_in[16];
    float* out = (float*)d_out;

    float *dWeff, *dbeff, *dWcomb, *dbcomb, *dqkv, *dctx, *dy;
    cudaGetSymbolAddress((void**)&dWeff,  g_Weff);
    cudaGetSymbolAddress((void**)&dbeff,  g_beff);
    cudaGetSymbolAddress((void**)&dWcomb, g_Wcomb);
    cudaGetSymbolAddress((void**)&dbcomb, g_bcomb);
    cudaGetSymbolAddress((void**)&dqkv,   g_qkv);
    cudaGetSymbolAddress((void**)&dctx,   g_ctx);
    cudaGetSymbolAddress((void**)&dy,     g_y);

    // 1. fold weights + biases
    prep_gemmAB<<<dim3(4, 4, 4), 256>>>(Win, Wq, Wk, Wv, Wfc, Wout);
    bias_kernel<<<128, 256>>>(Win, bin_, bq, bk, bv, Wfc, bout, bfc);

    // 2. fused qkv projection: [8192,256] @ [768,256]^T   (tf32 tensor cores)
    gemm_mma<<<dim3(LDQKV / 128, MROWS / 128), 256>>>(mod, dWeff, dbeff, nullptr, dqkv, LDQKV, ND);

    // 3. banded attention (tensor cores)
    attn_mma<<<dim3(SQ / 64, NB * NH), 64>>>(req, dctx);

    // 4. fused out_proj+fc with residual: ctx @ (Wfc@Wout)^T + bcomb + mod
    gemm_mma<<<dim3(ND / 128, MROWS / 128), 256>>>(dctx, dWcomb, dbcomb, mod, dy, ND, NE);

    // 5. layernorm
    ln_kernel<<<MROWS / 8, 256>>>(gamma, beta, out);
}

// round 5
// speedup vs baseline: 4.2868x; 1.1138x over previous
#include <cuda_runtime.h>
#include <math_constants.h>
#include <cstdint>

#define SQ 2048
#define NB 4
#define ND 256
#define NE 256
#define NH 8
#define HD 32
#define MROWS (SQ*NB)       // 8192
#define LDQKV (3*NE)        // 768

// ---------------- scratch (device globals; no allocation) ----------------
__device__ __align__(16) float g_Weff[3*NE*ND];
__device__ __align__(16) float g_beff[3*NE];
__device__ __align__(16) float g_Wcomb[ND*NE];
__device__ __align__(16) float g_bcomb[ND];
__device__ __align__(16) float g_qkv[(size_t)MROWS*LDQKV];
__device__ __align__(16) float g_ctx[(size_t)MROWS*NE];
__device__ __align__(16) float g_y[(size_t)MROWS*ND];

// ---------------- helpers ----------------
__device__ __forceinline__ void mma_tf32(float c[4],
                                         uint32_t a0, uint32_t a1, uint32_t a2, uint32_t a3,
                                         uint32_t b0, uint32_t b1)
{
    asm volatile("mma.sync.aligned.m16n8k8.row.col.f32.tf32.tf32.f32 "
                 "{%0,%1,%2,%3}, {%4,%5,%6,%7}, {%8,%9}, {%0,%1,%2,%3};"
                 : "+f"(c[0]), "+f"(c[1]), "+f"(c[2]), "+f"(c[3])
                 : "r"(a0), "r"(a1), "r"(a2), "r"(a3), "r"(b0), "r"(b1));
}

__device__ __forceinline__ void cp16(void* smem_dst, const void* gmem_src) {
    uint32_t sa = (uint32_t)__cvta_generic_to_shared(smem_dst);
    asm volatile("cp.async.cg.shared.global [%0], [%1], 16;\n" :: "r"(sa), "l"(gmem_src));
}

// ---------------- prep: 4 small 256x256x256 products, smem-tiled ----------------
__global__ void prep_gemmAB(const float* __restrict__ Win,
                            const float* __restrict__ Wq, const float* __restrict__ Wk,
                            const float* __restrict__ Wv, const float* __restrict__ Wfc,
                            const float* __restrict__ Wout)
{
    __shared__ __align__(16) float As[16][68];   // [c][r]
    __shared__ __align__(16) float Bs[16][68];   // [c][d]
    const int tt = blockIdx.z;
    const float* A; const float* B; float* C;
    if (tt < 3) { A = Win + (size_t)tt*NE*NE; B = (tt==0)?Wq:(tt==1)?Wk:Wv; C = g_Weff + (size_t)tt*NE*ND; }
    else        { A = Wfc; B = Wout; C = g_Wcomb; }

    const int t   = threadIdx.x;
    const int m0  = blockIdx.y * 64;
    const int d0  = blockIdx.x * 64;
    const int lrow = t >> 2;
    const int lc4  = (t & 3) << 2;
    const int brow = t >> 4;
    const int bc4  = (t & 15) << 2;
    const int ty = t >> 4, tx = t & 15;

    float acc[4][4] = {};
    for (int k0 = 0; k0 < NE; k0 += 16) {
        float4 av = *(const float4*)&A[(size_t)(m0 + lrow)*NE + k0 + lc4];
        As[lc4+0][lrow] = av.x; As[lc4+1][lrow] = av.y;
        As[lc4+2][lrow] = av.z; As[lc4+3][lrow] = av.w;
        *(float4*)&Bs[brow][bc4] = *(const float4*)&B[(size_t)(k0 + brow)*NE + d0 + bc4];
        __syncthreads();
        #pragma unroll
        for (int kk = 0; kk < 16; kk++) {
            float4 a4 = *(const float4*)&As[kk][ty << 2];
            float4 b4 = *(const float4*)&Bs[kk][tx << 2];
            float ar[4] = {a4.x, a4.y, a4.z, a4.w};
            float br[4] = {b4.x, b4.y, b4.z, b4.w};
            #pragma unroll
            for (int i = 0; i < 4; i++)
                #pragma unroll
                for (int j = 0; j < 4; j++)
                    acc[i][j] += ar[i] * br[j];
        }
        __syncthreads();
    }
    #pragma unroll
    for (int i = 0; i < 4; i++) {
        float4 o = {acc[i][0], acc[i][1], acc[i][2], acc[i][3]};
        *(float4*)&C[(size_t)(m0 + (ty<<2) + i)*NE + d0 + (tx<<2)] = o;
    }
}

// ---------------- bias fold: warp per output ----------------
__global__ void bias_kernel(const float* __restrict__ Win, const float* __restrict__ bin_,
                            const float* __restrict__ bq, const float* __restrict__ bk,
                            const float* __restrict__ bv, const float* __restrict__ Wfc,
                            const float* __restrict__ bout, const float* __restrict__ bfc)
{
    int wid = blockIdx.x * 8 + (threadIdx.x >> 5);
    int lane = threadIdx.x & 31;
    const float* row; const float* vec; float base;
    if (wid < 3*NE) {
        int t = wid >> 8;
        row = Win + (size_t)wid * NE;
        vec = (t == 0) ? bq : (t == 1) ? bk : bv;
        base = bin_[wid];
    } else {
        int r = wid - 3*NE;
        row = Wfc + (size_t)r * NE;
        vec = bout;
        base = bfc[r];
    }
    float s = 0.f;
    #pragma unroll
    for (int u = 0; u < 8; u++) s += row[u*32 + lane] * vec[u*32 + lane];
    #pragma unroll
    for (int o = 16; o >= 1; o >>= 1) s += __shfl_xor_sync(0xffffffffu, s, o);
    if (lane == 0) {
        if (wid < 3*NE) g_beff[wid] = base + s;
        else            g_bcomb[wid - 3*NE] = base + s;
    }
}

// ---------------- tensor-core GEMM, 2-stage cp.async pipeline ----------------
// C[M,N] = A[M,K] @ W[N,K]^T + bias (+resid). Block tile 128x128, BK=32,
// 256 threads, warp tile 64x32. Dynamic smem: 2 stages x (As+Bs) 128x36.
#define GST 36
#define GEMM_SMEM (4*128*GST*(int)sizeof(float))   // 73728 B
extern __shared__ float sdyn[];
__global__ void __launch_bounds__(256) gemm_mma(const float* __restrict__ A,
                                                const float* __restrict__ W,
                                                const float* __restrict__ bias,
                                                const float* __restrict__ resid,
                                                float* __restrict__ C, int N, int K)
{
    float* AsB = sdyn;                 // [2][128][GST]
    float* BsB = sdyn + 2*128*GST;     // [2][128][GST]
    const int tid = threadIdx.x;
    const int m0 = blockIdx.y * 128;
    const int n0 = blockIdx.x * 128;
    const int warp = tid >> 5;
    const int lane = tid & 31;
    const int wm = warp >> 2;
    const int wn = warp & 3;
    const int grp = lane >> 2;
    const int tig = lane & 3;
    const int ldr = tid >> 3;
    const int ldc = (tid & 7) << 2;

    const int T = K >> 5;
    float acc[4][4][4] = {};

    // prefetch stage 0
    {
        float* As = AsB; float* Bs = BsB;
        #pragma unroll
        for (int p = 0; p < 4; p++) {
            int row = ldr + p * 32;
            cp16(&As[row*GST + ldc], &A[(size_t)(m0 + row)*K + ldc]);
            cp16(&Bs[row*GST + ldc], &W[(size_t)(n0 + row)*K + ldc]);
        }
        asm volatile("cp.async.commit_group;\n");
    }

    for (int t = 0; t < T; t++) {
        if (t + 1 < T) {
            int buf = (t + 1) & 1;
            int k0 = (t + 1) << 5;
            float* As = AsB + buf*128*GST;
            float* Bs = BsB + buf*128*GST;
            #pragma unroll
            for (int p = 0; p < 4; p++) {
                int row = ldr + p * 32;
                cp16(&As[row*GST + ldc], &A[(size_t)(m0 + row)*K + k0 + ldc]);
                cp16(&Bs[row*GST + ldc], &W[(size_t)(n0 + row)*K + k0 + ldc]);
            }
            asm volatile("cp.async.commit_group;\n");
            asm volatile("cp.async.wait_group 1;\n");
        } else {
            asm volatile("cp.async.wait_group 0;\n");
        }
        __syncthreads();

        const float* As = AsB + (t & 1)*128*GST;
        const float* Bs = BsB + (t & 1)*128*GST;
        #pragma unroll
        for (int kk = 0; kk < 32; kk += 8) {
            uint32_t af[4][4], bf[4][2];
            #pragma unroll
            for (int mt = 0; mt < 4; mt++) {
                int r = (wm*64 + mt*16 + grp) * GST;
                af[mt][0] = __float_as_uint(As[r + kk + tig]);
                af[mt][1] = __float_as_uint(As[r + 8*GST + kk + tig]);
                af[mt][2] = __float_as_uint(As[r + kk + 4 + tig]);
                af[mt][3] = __float_as_uint(As[r + 8*GST + kk + 4 + tig]);
            }
            #pragma unroll
            for (int nt = 0; nt < 4; nt++) {
                int c = (wn*32 + nt*8 + grp) * GST;
                bf[nt][0] = __float_as_uint(Bs[c + kk + tig]);
                bf[nt][1] = __float_as_uint(Bs[c + kk + 4 + tig]);
            }
            #pragma unroll
            for (int mt = 0; mt < 4; mt++)
                #pragma unroll
                for (int nt = 0; nt < 4; nt++)
                    mma_tf32(acc[mt][nt], af[mt][0], af[mt][1], af[mt][2], af[mt][3],
                             bf[nt][0], bf[nt][1]);
        }
        __syncthreads();
    }

    #pragma unroll
    for (int mt = 0; mt < 4; mt++) {
        #pragma unroll
        for (int nt = 0; nt < 4; nt++) {
            int col = n0 + wn*32 + nt*8 + 2*tig;
            float bx = bias[col], by = bias[col + 1];
            int r0 = m0 + wm*64 + mt*16 + grp;
            float2 o0 = {acc[mt][nt][0] + bx, acc[mt][nt][1] + by};
            float2 o1 = {acc[mt][nt][2] + bx, acc[mt][nt][3] + by};
            if (resid) {
                float2 r0v = *(const float2*)&resid[(size_t)r0 * N + col];
                float2 r1v = *(const float2*)&resid[(size_t)(r0 + 8) * N + col];
                o0.x += r0v.x; o0.y += r0v.y;
                o1.x += r1v.x; o1.y += r1v.y;
            }
            *(float2*)&C[(size_t)r0 * N + col] = o0;
            *(float2*)&C[(size_t)(r0 + 8) * N + col] = o1;
        }
    }
}

// ---------------- banded attention via tensor cores ----------------
// Block: 64 queries x one (b,h), 128 threads (4 warps), warp owns 16 queries.
// Per warp: S[16x64] = Q @ K^T over a 64-key window starting at wbase+w*16,
// masked softmax in registers, C[16x32] = P @ V. Supports req <= 24.
#define KST 36     // sK row stride
#define VST 116    // sVT row stride (mod 32 = 20, conflict-free for frag reads)
#define QST 36     // sQ row stride
#define PST 68     // sP row stride
#define KROWS 112
__global__ void __launch_bounds__(128) attn_mma(const int* __restrict__ reqp,
                                                float* __restrict__ ctx)
{
    __shared__ float sK[KROWS*KST];    // keys [wbase..wbase+112) x 32 dims
    __shared__ float sVT[32*VST];      // dims x 112 keys (transposed V)
    __shared__ float sU[4352];         // union: Q[64][36] then P[4][16][68]

    const float* qkv = g_qkv;
    const int req = *reqp;
    const int bh = blockIdx.y;
    const int b = bh >> 3;
    const int hoff = (bh & 7) * HD;
    const int q0 = blockIdx.x * 64;
    const int wbase = q0 - (req - 1);

    const int tid = threadIdx.x;
    const int w = tid >> 5;
    const int lane = tid & 31;
    const int grp = lane >> 2;
    const int tig = lane & 3;
    const float scale = rsqrtf((float)HD);

    // ---- stage Q (scaled), K, V^T (raw f32; MMA truncates to tf32) ----
    #pragma unroll
    for (int u = tid; u < 512; u += 128) {           // Q: 64 rows x 8 float4
        int r = u >> 3, c4 = (u & 7) << 2;
        float4 v = *(const float4*)&qkv[(size_t)((q0 + r)*NB + b)*LDQKV + hoff + c4];
        sU[r*QST + c4 + 0] = v.x * scale;
        sU[r*QST + c4 + 1] = v.y * scale;
        sU[r*QST + c4 + 2] = v.z * scale;
        sU[r*QST + c4 + 3] = v.w * scale;
    }
    #pragma unroll
    for (int u = tid; u < KROWS*8; u += 128) {       // K + V: 112 rows x 8 float4
        int r = u >> 3, c4 = (u & 7) << 2;
        int key = wbase + r;
        float4 kv = {0.f, 0.f, 0.f, 0.f}, vv = {0.f, 0.f, 0.f, 0.f};
        if (key >= 0 && key < SQ) {
            size_t base = (size_t)(key*NB + b)*LDQKV + hoff + c4;
            kv = *(const float4*)&qkv[base + NE];
            vv = *(const float4*)&qkv[base + 2*NE];
        }
        sK[r*KST + c4 + 0] = kv.x;
        sK[r*KST + c4 + 1] = kv.y;
        sK[r*KST + c4 + 2] = kv.z;
        sK[r*KST + c4 + 3] = kv.w;
        sVT[(c4+0)*VST + r] = vv.x;
        sVT[(c4+1)*VST + r] = vv.y;
        sVT[(c4+2)*VST + r] = vv.z;
        sVT[(c4+3)*VST + r] = vv.w;
    }
    __syncthreads();

    // ---- scores: S[16x64] = Q @ K^T (keys wbase + w*16 + 0..63) ----
    float sc[8][4] = {};
    #pragma unroll
    for (int ks = 0; ks < 4; ks++) {
        int kk = ks * 8;
        uint32_t af[4], bf[8][2];
        {
            int r = (w*16 + grp) * QST;
            af[0] = __float_as_uint(sU[r + kk + tig]);
            af[1] = __float_as_uint(sU[r + 8*QST + kk + tig]);
            af[2] = __float_as_uint(sU[r + kk + 4 + tig]);
            af[3] = __float_as_uint(sU[r + 8*QST + kk + 4 + tig]);
        }
        #pragma unroll
        for (int nt = 0; nt < 8; nt++) {
            int r = (w*16 + nt*8 + grp) * KST;
            bf[nt][0] = __float_as_uint(sK[r + kk + tig]);
            bf[nt][1] = __float_as_uint(sK[r + kk + 4 + tig]);
        }
        #pragma unroll
        for (int nt = 0; nt < 8; nt++)
            mma_tf32(sc[nt], af[0], af[1], af[2], af[3], bf[nt][0], bf[nt][1]);
    }

    // ---- mask + softmax (registers) ----
    const int iw = q0 + w*16;
    const int jw = wbase + w*16;
    float mx0 = -CUDART_INF_F, mx1 = -CUDART_INF_F;
    {
        int i0 = iw + grp, i1 = i0 + 8;
        #pragma unroll
        for (int nt = 0; nt < 8; nt++) {
            int j0 = jw + nt*8 + 2*tig;
            int j1 = j0 + 1;
            bool g0 = (j0 >= 0) & (j0 < SQ);
            bool g1 = (j1 >= 0) & (j1 < SQ);
            float* c = sc[nt];
            c[0] = (g0 && abs(i0 - j0) < req) ? c[0] : -CUDART_INF_F;
            c[1] = (g1 && abs(i0 - j1) < req) ? c[1] : -CUDART_INF_F;
            c[2] = (g0 && abs(i1 - j0) < req) ? c[2] : -CUDART_INF_F;
            c[3] = (g1 && abs(i1 - j1) < req) ? c[3] : -CUDART_INF_F;
            mx0 = fmaxf(mx0, fmaxf(c[0], c[1]));
            mx1 = fmaxf(mx1, fmaxf(c[2], c[3]));
        }
    }
    #pragma unroll
    for (int o = 1; o <= 2; o <<= 1) {
        mx0 = fmaxf(mx0, __shfl_xor_sync(0xffffffffu, mx0, o));
        mx1 = fmaxf(mx1, __shfl_xor_sync(0xffffffffu, mx1, o));
    }
    float s0 = 0.f, s1 = 0.f;
    #pragma unroll
    for (int nt = 0; nt < 8; nt++) {
        float* c = sc[nt];
        c[0] = __expf(c[0] - mx0);
        c[1] = __expf(c[1] - mx0);
        c[2] = __expf(c[2] - mx1);
        c[3] = __expf(c[3] - mx1);
        s0 += c[0] + c[1];
        s1 += c[2] + c[3];
    }
    #pragma unroll
    for (int o = 1; o <= 2; o <<= 1) {
        s0 += __shfl_xor_sync(0xffffffffu, s0, o);
        s1 += __shfl_xor_sync(0xffffffffu, s1, o);
    }
    float rs0 = 1.f / s0, rs1 = 1.f / s1;

    // ---- store P into union region (overwrites Q) ----
    __syncthreads();   // all warps done reading sQ
    float* sP = sU + w * (16*PST);
    #pragma unroll
    for (int nt = 0; nt < 8; nt++) {
        float* c = sc[nt];
        int r0 = grp * PST + nt*8 + 2*tig;
        *(float2*)&sP[r0]           = make_float2(c[0], c[1]);
        *(float2*)&sP[r0 + 8*PST]   = make_float2(c[2], c[3]);
    }
    __syncwarp();

    // ---- ctx: C[16x32] = P[16x64] @ V[64x32] ----
    float ao[4][4] = {};
    #pragma unroll
    for (int ks = 0; ks < 8; ks++) {
        int kk = ks * 8;
        uint32_t af[4], bf[4][2];
        af[0] = __float_as_uint(sP[grp*PST + kk + tig]);
        af[1] = __float_as_uint(sP[(grp+8)*PST + kk + tig]);
        af[2] = __float_as_uint(sP[grp*PST + kk + 4 + tig]);
        af[3] = __float_as_uint(sP[(grp+8)*PST + kk + 4 + tig]);
        #pragma unroll
        for (int nt = 0; nt < 4; nt++) {
            int r = (nt*8 + grp) * VST + w*16;
            bf[nt][0] = __float_as_uint(sVT[r + kk + tig]);
            bf[nt][1] = __float_as_uint(sVT[r + kk + 4 + tig]);
        }
        #pragma unroll
        for (int nt = 0; nt < 4; nt++)
            mma_tf32(ao[nt], af[0], af[1], af[2], af[3], bf[nt][0], bf[nt][1]);
    }

    // ---- epilogue: divide by row sums, write ctx ----
    {
        int i0 = iw + grp;
        #pragma unroll
        for (int nt = 0; nt < 4; nt++) {
            int dcol = hoff + nt*8 + 2*tig;
            float2 o0 = {ao[nt][0] * rs0, ao[nt][1] * rs0};
            float2 o1 = {ao[nt][2] * rs1, ao[nt][3] * rs1};
            *(float2*)&ctx[(size_t)(i0*NB + b)*NE + dcol] = o0;
            *(float2*)&ctx[(size_t)((i0 + 8)*NB + b)*NE + dcol] = o1;
        }
    }
}

// ---------------- layernorm (warp per row of 256) ----------------
__global__ void ln_kernel(const float* __restrict__ gamma, const float* __restrict__ beta,
                          float* __restrict__ out)
{
    int row = blockIdx.x * 8 + (threadIdx.x >> 5);
    int lane = threadIdx.x & 31;
    const float* yr = g_y + (size_t)row * ND;
    float v[8], s = 0.f, s2 = 0.f;
    #pragma unroll
    for (int u = 0; u < 8; u++) {
        v[u] = yr[u * 32 + lane];
        s += v[u];
        s2 += v[u] * v[u];
    }
    #pragma unroll
    for (int o = 16; o >= 1; o >>= 1) {
        s  += __shfl_xor_sync(0xffffffffu, s, o);
        s2 += __shfl_xor_sync(0xffffffffu, s2, o);
    }
    float mu  = s * (1.f / ND);
    float var = s2 * (1.f / ND) - mu * mu;
    float inv = rsqrtf(var + 1e-6f);
    #pragma unroll
    for (int u = 0; u < 8; u++) {
        int c = u * 32 + lane;
        out[(size_t)row * ND + c] = (v[u] - mu) * inv * gamma[c] + beta[c];
    }
}

// ---------------- launch ----------------
extern "C" void kernel_launch(void* const* d_in, const int* in_sizes, int n_in,
                              void* d_out, int out_size)
{
    const float* mod  = (const float*)d_in[0];
    const float* Wq   = (const float*)d_in[2];
    const float* bq   = (const float*)d_in[3];
    const float* Wk   = (const float*)d_in[4];
    const float* bk   = (const float*)d_in[5];
    const float* Wv   = (const float*)d_in[6];
    const float* bv   = (const float*)d_in[7];
    const float* Win  = (const float*)d_in[8];
    const float* bin_ = (const float*)d_in[9];
    const float* Wout = (const float*)d_in[10];
    const float* bout = (const float*)d_in[11];
    const float* Wfc  = (const float*)d_in[12];
    const float* bfc  = (const float*)d_in[13];
    const float* gamma= (const float*)d_in[14];
    const float* beta = (const float*)d_in[15];
    const int*   req  = (const int*)d_in[16];
    float* out = (float*)d_out;

    float *dWeff, *dbeff, *dWcomb, *dbcomb, *dqkv, *dctx, *dy;
    cudaGetSymbolAddress((void**)&dWeff,  g_Weff);
    cudaGetSymbolAddress((void**)&dbeff,  g_beff);
    cudaGetSymbolAddress((void**)&dWcomb, g_Wcomb);
    cudaGetSymbolAddress((void**)&dbcomb, g_bcomb);
    cudaGetSymbolAddress((void**)&dqkv,   g_qkv);
    cudaGetSymbolAddress((void**)&dctx,   g_ctx);
    cudaGetSymbolAddress((void**)&dy,     g_y);

    static int smem_set = 0;
    if (!smem_set) {
        cudaFuncSetAttribute(gemm_mma, cudaFuncAttributeMaxDynamicSharedMemorySize, GEMM_SMEM);
        smem_set = 1;
    }

    // 1. fold weights + biases
    prep_gemmAB<<<dim3(4, 4, 4), 256>>>(Win, Wq, Wk, Wv, Wfc, Wout);
    bias_kernel<<<128, 256>>>(Win, bin_, bq, bk, bv, Wfc, bout, bfc);

    // 2. fused qkv projection: [8192,256] @ [768,256]^T   (tf32, cp.async pipelined)
    gemm_mma<<<dim3(LDQKV / 128, MROWS / 128), 256, GEMM_SMEM>>>(mod, dWeff, dbeff, nullptr, dqkv, LDQKV, ND);

    // 3. banded attention (tensor cores)
    attn_mma<<<dim3(SQ / 64, NB * NH), 128>>>(req, dctx);

    // 4. fused out_proj+fc with residual: ctx @ (Wfc@Wout)^T + bcomb + mod
    gemm_mma<<<dim3(ND / 128, MROWS / 128), 256, GEMM_SMEM>>>(dctx, dWcomb, dbcomb, mod, dy, ND, NE);

    // 5. layernorm
    ln_kernel<<<MROWS / 8, 256>>>(gamma, beta, out);
}